// round 1
// baseline (speedup 1.0000x reference)
#include <cuda_runtime.h>
#include <math.h>

#define Bn 16
#define Tn 1024
#define Cn 384
#define Hn 6
#define Dn 64
#define BH (Bn*Hn)

// scratch: [B,H,T,D] each = 6.29M floats (25.2 MB)
__device__ float g_q[BH*Tn*Dn];
__device__ float g_k[BH*Tn*Dn];
__device__ float g_v[BH*Tn*Dn];
__device__ float g_attn[BH*Tn*Dn];

// ---------------------------------------------------------------------------
// Kernel 1: QKV projection.  X[16384,384] @ W[h][384,64] for 3 mats x 6 heads.
// grid = (256 m-tiles, 18 = mat*6+h), block = 256 threads, 64x64 tile, 4x4 micro.
// ---------------------------------------------------------------------------
__global__ void qkv_kernel(const float* __restrict__ x,
                           const float* __restrict__ wq,
                           const float* __restrict__ wk,
                           const float* __restrict__ wv)
{
    __shared__ float As[16][65];   // [k][m] transposed
    __shared__ float Bs[16][64];   // [k][n]

    const int mt  = blockIdx.x;          // 0..255
    const int nt  = blockIdx.y;          // 0..17
    const int mat = nt / Hn;
    const int h   = nt % Hn;
    const float* w = (mat == 0 ? wq : (mat == 1 ? wk : wv)) + h * Cn * Dn;
    float* out = (mat == 0 ? g_q : (mat == 1 ? g_k : g_v));

    const int tid = threadIdx.x;
    const int ty = tid >> 4, tx = tid & 15;
    const int m0 = mt * 64;

    float acc[4][4] = {};

    for (int k0 = 0; k0 < Cn; k0 += 16) {
        #pragma unroll
        for (int i = 0; i < 4; i++) {
            int idx = tid + i * 256;
            int ml = idx >> 4, kl = idx & 15;
            As[kl][ml] = x[(m0 + ml) * Cn + k0 + kl];
        }
        #pragma unroll
        for (int i = 0; i < 4; i++) {
            int idx = tid + i * 256;
            int kl = idx >> 6, d = idx & 63;
            Bs[kl][d] = w[(k0 + kl) * Dn + d];
        }
        __syncthreads();
        #pragma unroll
        for (int kk = 0; kk < 16; kk++) {
            float a[4], bb[4];
            #pragma unroll
            for (int i = 0; i < 4; i++) a[i] = As[kk][ty * 4 + i];
            #pragma unroll
            for (int j = 0; j < 4; j++) bb[j] = Bs[kk][tx * 4 + j];
            #pragma unroll
            for (int i = 0; i < 4; i++)
                #pragma unroll
                for (int j = 0; j < 4; j++)
                    acc[i][j] += a[i] * bb[j];
        }
        __syncthreads();
    }

    #pragma unroll
    for (int i = 0; i < 4; i++) {
        int m = m0 + ty * 4 + i;
        int b = m / Tn, t = m % Tn;
        float* orow = out + ((b * Hn + h) * Tn + t) * Dn;
        #pragma unroll
        for (int j = 0; j < 4; j++)
            orow[tx * 4 + j] = acc[i][j];
    }
}

// ---------------------------------------------------------------------------
// Kernel 2: flash attention (no mask). grid = (16 q-tiles, 96 bh), 256 threads.
// BLOCK_M = BLOCK_N = 64, D = 64. Dynamic smem: 4 * 64*65 floats = 66560 B.
// ---------------------------------------------------------------------------
__global__ void attn_kernel()
{
    extern __shared__ float sm[];
    float* Qs = sm;                 // [64][65]
    float* Ks = Qs + 64 * 65;
    float* Vs = Ks + 64 * 65;
    float* Ps = Vs + 64 * 65;

    const int qt = blockIdx.x;
    const int bh = blockIdx.y;
    const float* qb = g_q + bh * Tn * Dn;
    const float* kb = g_k + bh * Tn * Dn;
    const float* vb = g_v + bh * Tn * Dn;

    const int tid = threadIdx.x;
    const int ty = tid >> 4, tx = tid & 15;
    const float scale = 0.05103103630798287f;   // 1/sqrt(384)

    // load Q tile once
    #pragma unroll
    for (int i = 0; i < 16; i++) {
        int idx = tid + i * 256;
        int r = idx >> 6, d = idx & 63;
        Qs[r * 65 + d] = qb[(qt * 64 + r) * Dn + d];
    }

    float m_i[4], l_i[4], o[4][4] = {};
    #pragma unroll
    for (int i = 0; i < 4; i++) { m_i[i] = -1e30f; l_i[i] = 0.f; }

    for (int kt = 0; kt < Tn / 64; kt++) {
        __syncthreads();   // prev iter's O-compute done before K/V overwrite
        #pragma unroll
        for (int i = 0; i < 16; i++) {
            int idx = tid + i * 256;
            int r = idx >> 6, d = idx & 63;
            Ks[r * 65 + d] = kb[(kt * 64 + r) * Dn + d];
            Vs[r * 65 + d] = vb[(kt * 64 + r) * Dn + d];
        }
        __syncthreads();

        // S = Q K^T (4x4 per thread)
        float s[4][4] = {};
        #pragma unroll 8
        for (int d = 0; d < 64; d++) {
            float a[4], bb[4];
            #pragma unroll
            for (int i = 0; i < 4; i++) a[i]  = Qs[(ty * 4 + i) * 65 + d];
            #pragma unroll
            for (int j = 0; j < 4; j++) bb[j] = Ks[(tx * 4 + j) * 65 + d];
            #pragma unroll
            for (int i = 0; i < 4; i++)
                #pragma unroll
                for (int j = 0; j < 4; j++)
                    s[i][j] += a[i] * bb[j];
        }

        // online softmax per row (rows ty*4+i, reduce across 16 tx lanes)
        #pragma unroll
        for (int i = 0; i < 4; i++) {
            float rmax = -1e30f;
            #pragma unroll
            for (int j = 0; j < 4; j++) {
                s[i][j] *= scale;
                rmax = fmaxf(rmax, s[i][j]);
            }
            #pragma unroll
            for (int off = 8; off >= 1; off >>= 1)
                rmax = fmaxf(rmax, __shfl_xor_sync(0xffffffffu, rmax, off));

            float mn = fmaxf(m_i[i], rmax);
            float corr = __expf(m_i[i] - mn);
            float rsum = 0.f;
            #pragma unroll
            for (int j = 0; j < 4; j++) {
                float p = __expf(s[i][j] - mn);
                Ps[(ty * 4 + i) * 65 + tx * 4 + j] = p;
                rsum += p;
            }
            #pragma unroll
            for (int off = 8; off >= 1; off >>= 1)
                rsum += __shfl_xor_sync(0xffffffffu, rsum, off);

            l_i[i] = l_i[i] * corr + rsum;
            m_i[i] = mn;
            #pragma unroll
            for (int j = 0; j < 4; j++) o[i][j] *= corr;
        }
        __syncthreads();   // all P written

        // O += P V
        #pragma unroll 8
        for (int ss = 0; ss < 64; ss++) {
            float a[4], bb[4];
            #pragma unroll
            for (int i = 0; i < 4; i++) a[i]  = Ps[(ty * 4 + i) * 65 + ss];
            #pragma unroll
            for (int j = 0; j < 4; j++) bb[j] = Vs[ss * 65 + tx * 4 + j];
            #pragma unroll
            for (int i = 0; i < 4; i++)
                #pragma unroll
                for (int j = 0; j < 4; j++)
                    o[i][j] += a[i] * bb[j];
        }
    }

    #pragma unroll
    for (int i = 0; i < 4; i++) {
        float inv = 1.f / l_i[i];
        int r = qt * 64 + ty * 4 + i;
        float* orow = g_attn + (bh * Tn + r) * Dn;
        #pragma unroll
        for (int j = 0; j < 4; j++)
            orow[tx * 4 + j] = o[i][j] * inv;
    }
}

// ---------------------------------------------------------------------------
// Kernel 3: output projection.  A_cat[16384, 384] @ wp^T + bp -> out.
// A[m][k] with k = h*64+d gathered from g_attn [B,H,T,D].
// grid = (256, 6), block 256, 64x64 tile.
// ---------------------------------------------------------------------------
__global__ void proj_kernel(const float* __restrict__ wp,
                            const float* __restrict__ bp,
                            float* __restrict__ out)
{
    __shared__ float As[16][65];   // [k][m]
    __shared__ float Bs[16][65];   // [k][n]

    const int mt = blockIdx.x;
    const int nt = blockIdx.y;
    const int tid = threadIdx.x;
    const int ty = tid >> 4, tx = tid & 15;
    const int m0 = mt * 64, n0 = nt * 64;

    float acc[4][4] = {};

    for (int k0 = 0; k0 < Cn; k0 += 16) {
        #pragma unroll
        for (int i = 0; i < 4; i++) {
            int idx = tid + i * 256;
            int ml = idx >> 4, kl = idx & 15;
            int m = m0 + ml, k = k0 + kl;
            int b = m / Tn, t = m % Tn;
            int h = k >> 6, d = k & 63;
            As[kl][ml] = g_attn[((b * Hn + h) * Tn + t) * Dn + d];
        }
        #pragma unroll
        for (int i = 0; i < 4; i++) {
            int idx = tid + i * 256;
            int nl = idx >> 4, kl = idx & 15;
            Bs[kl][nl] = wp[(n0 + nl) * Cn + k0 + kl];
        }
        __syncthreads();
        #pragma unroll
        for (int kk = 0; kk < 16; kk++) {
            float a[4], bb[4];
            #pragma unroll
            for (int i = 0; i < 4; i++) a[i]  = As[kk][ty * 4 + i];
            #pragma unroll
            for (int j = 0; j < 4; j++) bb[j] = Bs[kk][tx * 4 + j];
            #pragma unroll
            for (int i = 0; i < 4; i++)
                #pragma unroll
                for (int j = 0; j < 4; j++)
                    acc[i][j] += a[i] * bb[j];
        }
        __syncthreads();
    }

    #pragma unroll
    for (int i = 0; i < 4; i++) {
        int m = m0 + ty * 4 + i;
        #pragma unroll
        for (int j = 0; j < 4; j++) {
            int n = n0 + tx * 4 + j;
            out[m * Cn + n] = acc[i][j] + bp[n];
        }
    }
}

// ---------------------------------------------------------------------------
extern "C" void kernel_launch(void* const* d_in, const int* in_sizes, int n_in,
                              void* d_out, int out_size)
{
    const float* x  = (const float*)d_in[0];
    const float* wq = (const float*)d_in[1];
    const float* wk = (const float*)d_in[2];
    const float* wv = (const float*)d_in[3];
    const float* wp = (const float*)d_in[4];
    const float* bp = (const float*)d_in[5];
    float* out = (float*)d_out;

    qkv_kernel<<<dim3(256, 18), 256>>>(x, wq, wk, wv);

    const int attn_smem = 4 * 64 * 65 * (int)sizeof(float);   // 66560 B
    cudaFuncSetAttribute(attn_kernel,
                         cudaFuncAttributeMaxDynamicSharedMemorySize, attn_smem);
    attn_kernel<<<dim3(Tn / 64, BH), 256, attn_smem>>>();

    proj_kernel<<<dim3(256, 6), 256>>>(wp, bp, out);
}